// round 9
// baseline (speedup 1.0000x reference)
#include <cuda_runtime.h>

#define BATCH 16
#define NROW  16384
#define DIM   128
#define KPT   10
#define SROWS 512                 // rows per score block (4 per thread)
#define NBLK  32                  // 16384 / 512
#define MCH   32                  // mean-kernel chunks (512 rows each)
#define SCALE_F 0.08838834764831843f  // 1/sqrt(128)

// ---------------- scratch (static device memory: allowed) ----------------
// column-sum partials: side1 from mean pass, side0 fused into score pass (32 chunks each)
__device__ float g_cs[2][BATCH][NBLK][DIM];
__device__ float g_v[2][BATCH][KPT][DIM];
__device__ float g_part[2][BATCH][KPT][NBLK][5];
__device__ float g_Y[2][BATCH][KPT][3];

// ---------------- pass 1: column sums of H2 only ----------------
__global__ void mean_kernel(const float* __restrict__ H2) {
    int chunk = blockIdx.x, b = blockIdx.y;
    int t = threadIdx.x;
    int col4 = t & 31, rl = t >> 5;
    const float4* base = (const float4*)(H2 + ((size_t)b * NROW + (size_t)chunk * 512) * DIM);
    float s0 = 0.f, s1 = 0.f, s2 = 0.f, s3 = 0.f;
#pragma unroll 8
    for (int r = rl; r < 512; r += 8) {
        float4 v = base[(size_t)r * 32 + col4];
        s0 += v.x; s1 += v.y; s2 += v.z; s3 += v.w;
    }
    __shared__ float red[256][4];
    red[t][0] = s0; red[t][1] = s1; red[t][2] = s2; red[t][3] = s3;
    __syncthreads();
    if (t < 32) {
        float a0 = red[t][0], a1 = red[t][1], a2 = red[t][2], a3 = red[t][3];
#pragma unroll
        for (int m = 1; m < 8; m++) {
            a0 += red[t + 32 * m][0]; a1 += red[t + 32 * m][1];
            a2 += red[t + 32 * m][2]; a3 += red[t + 32 * m][3];
        }
        float* o = &g_cs[1][b][chunk][t * 4];
        o[0] = a0; o[1] = a1; o[2] = a2; o[3] = a3;
    }
}

// ---------------- fused hbar + v ----------------
// v[side][b][k][d] = scale * sum_e W_side[k][d][e] * hbar[side^1][b][e]
__global__ void v_kernel(const float* __restrict__ W, int side) {
    int k = blockIdx.x, b = blockIdx.y;
    __shared__ float hb[DIM];
    int d = threadIdx.x;
    {
        float s = 0.f;
        const float* cs = &g_cs[side ^ 1][b][0][d];
#pragma unroll
        for (int c = 0; c < NBLK; c++) s += cs[c * DIM];   // 32 independent loads, full MLP
        hb[d] = s * (1.0f / NROW);
    }
    __syncthreads();
    const float4* wr = (const float4*)(W + ((size_t)k * DIM + d) * DIM);
    float acc = 0.f;
#pragma unroll
    for (int e4 = 0; e4 < 32; e4++) {     // fully unrolled: one memory round-trip
        float4 w = __ldg(&wr[e4]);
        acc += w.x * hb[e4 * 4 + 0] + w.y * hb[e4 * 4 + 1]
             + w.z * hb[e4 * 4 + 2] + w.w * hb[e4 * 4 + 3];
    }
    g_v[side][b][k][d] = acc * SCALE_F;
}

// ---------------- pass 2: scores + online softmax (+ fused colsum on side 0) ----------------
union U64F2 { unsigned long long u; float2 f; };

__device__ __forceinline__ void osm_combine(float& m, float& l, float& a0, float& a1, float& a2,
                                            float m2, float l2, float b0, float b1, float b2) {
    float mn = fmaxf(m, m2);
    float f1 = __expf(m - mn), f2 = __expf(m2 - mn);
    m = mn;
    l = l * f1 + l2 * f2;
    a0 = a0 * f1 + b0 * f2;
    a1 = a1 * f1 + b1 * f2;
    a2 = a2 * f1 + b2 * f2;
}

__global__ __launch_bounds__(128, 2) void score_kernel(
    const float* __restrict__ H, const float* __restrict__ X, int side) {
    int chunk = blockIdx.x, b = blockIdx.y;
    int t = threadIdx.x;
    int row0 = chunk * SROWS;

    __shared__ float vs[KPT * DIM];       // 5120 B
    __shared__ float tile[SROWS * 38];    // 77824 B, stride 38 -> conflict-free LDS.64
    __shared__ float red[4][KPT][5];      // 800 B
    __shared__ float csum[4][32];         // 512 B   (total ~84.3 KB -> 2 blocks/SM)

    {   // load v tile (coalesced)
        const float4* vg = (const float4*)&g_v[side][b][0][0];
        float4* vd = (float4*)vs;
        for (int i = t; i < KPT * DIM / 4; i += 128) vd[i] = vg[i];
    }

    unsigned long long acc[4][KPT];
#pragma unroll
    for (int r = 0; r < 4; r++)
#pragma unroll
        for (int k = 0; k < KPT; k++) acc[r][k] = 0ull;

    const float* Hb = H + ((size_t)b * NROW + row0) * DIM;

    for (int c = 0; c < 4; c++) {
        __syncthreads();
        // stage 512 rows x 32 floats (chunk c of d), coalesced LDG.128
#pragma unroll
        for (int i = 0; i < 32; i++) {
            int t2 = t + 128 * i;
            int r = t2 >> 3, j = t2 & 7;
            float4 val = *(const float4*)(Hb + (size_t)r * DIM + c * 32 + j * 4);
            float* dst = &tile[r * 38 + j * 4];
            *(float2*)dst = make_float2(val.x, val.y);
            *(float2*)(dst + 2) = make_float2(val.z, val.w);
        }
        __syncthreads();

        const float* vb = vs + c * 32;
#pragma unroll
        for (int j = 0; j < 16; j++) {
            unsigned long long v[KPT];
#pragma unroll
            for (int k = 0; k < KPT; k++)
                v[k] = *(const unsigned long long*)&vb[k * DIM + 2 * j];   // broadcast LDS.64
#pragma unroll
            for (int r = 0; r < 4; r++) {
                unsigned long long x =
                    *(const unsigned long long*)&tile[(t + 128 * r) * 38 + 2 * j];
#pragma unroll
                for (int k = 0; k < KPT; k++)
                    asm("fma.rn.f32x2 %0, %1, %2, %0;" : "+l"(acc[r][k]) : "l"(x), "l"(v[k]));
            }
        }

        if (side == 0) {
            // fused column sums of this tile chunk (cols c*32 .. c*32+31)
            int col = t & 31, q = t >> 5;
            float s = 0.f;
            int rbase = q * 128;
#pragma unroll 8
            for (int r = 0; r < 128; r++) s += tile[(rbase + r) * 38 + col];
            csum[q][col] = s;
            __syncthreads();
            if (t < 32)
                g_cs[0][b][chunk][c * 32 + t] = csum[0][t] + csum[1][t] + csum[2][t] + csum[3][t];
        }
    }

    // per-thread rows: row0 + t + 128*r
    const float* Xb = X + ((size_t)b * NROW + row0) * 3;
    float xr[4][3];
#pragma unroll
    for (int r = 0; r < 4; r++) {
        xr[r][0] = Xb[(t + 128 * r) * 3 + 0];
        xr[r][1] = Xb[(t + 128 * r) * 3 + 1];
        xr[r][2] = Xb[(t + 128 * r) * 3 + 2];
    }

    int w = t >> 5, lane = t & 31;
#pragma unroll
    for (int k = 0; k < KPT; k++) {
        float s[4];
#pragma unroll
        for (int r = 0; r < 4; r++) {
            U64F2 u; u.u = acc[r][k];
            s[r] = u.f.x + u.f.y;
        }
        float m = fmaxf(fmaxf(s[0], s[1]), fmaxf(s[2], s[3]));
        float l = 0.f, a0 = 0.f, a1 = 0.f, a2 = 0.f;
#pragma unroll
        for (int r = 0; r < 4; r++) {
            float e = __expf(s[r] - m);
            l += e;
            a0 += e * xr[r][0];
            a1 += e * xr[r][1];
            a2 += e * xr[r][2];
        }
#pragma unroll
        for (int off = 16; off > 0; off >>= 1) {
            float m2 = __shfl_xor_sync(0xffffffffu, m, off);
            float l2 = __shfl_xor_sync(0xffffffffu, l, off);
            float b0 = __shfl_xor_sync(0xffffffffu, a0, off);
            float b1 = __shfl_xor_sync(0xffffffffu, a1, off);
            float b2 = __shfl_xor_sync(0xffffffffu, a2, off);
            osm_combine(m, l, a0, a1, a2, m2, l2, b0, b1, b2);
        }
        if (lane == 0) {
            red[w][k][0] = m; red[w][k][1] = l;
            red[w][k][2] = a0; red[w][k][3] = a1; red[w][k][4] = a2;
        }
    }
    __syncthreads();
    if (t < KPT) {
        float m = red[0][t][0], l = red[0][t][1];
        float a0 = red[0][t][2], a1 = red[0][t][3], a2 = red[0][t][4];
#pragma unroll
        for (int w2 = 1; w2 < 4; w2++)
            osm_combine(m, l, a0, a1, a2,
                        red[w2][t][0], red[w2][t][1], red[w2][t][2], red[w2][t][3], red[w2][t][4]);
        float* o = &g_part[side][b][t][chunk][0];
        o[0] = m; o[1] = l; o[2] = a0; o[3] = a1; o[4] = a2;
    }
}

// ---------------- combine partials -> Y ----------------
__global__ void combine_kernel() {
    int side = blockIdx.x, b = blockIdx.y;
    int k = threadIdx.x >> 5, lane = threadIdx.x & 31;
    const float* p = &g_part[side][b][k][lane][0];   // NBLK = 32: one partial per lane
    float m = p[0], l = p[1], a0 = p[2], a1 = p[3], a2 = p[4];
#pragma unroll
    for (int off = 16; off > 0; off >>= 1) {
        float m2 = __shfl_xor_sync(0xffffffffu, m, off);
        float l2 = __shfl_xor_sync(0xffffffffu, l, off);
        float b0 = __shfl_xor_sync(0xffffffffu, a0, off);
        float b1 = __shfl_xor_sync(0xffffffffu, a1, off);
        float b2 = __shfl_xor_sync(0xffffffffu, a2, off);
        osm_combine(m, l, a0, a1, a2, m2, l2, b0, b1, b2);
    }
    if (lane == 0) {
        float inv = 1.0f / l;
        g_Y[side][b][k][0] = a0 * inv;
        g_Y[side][b][k][1] = a1 * inv;
        g_Y[side][b][k][2] = a2 * inv;
    }
}

// ---------------- Kabsch (fp32, 3x3 Jacobi) ----------------
__global__ void kabsch_kernel(float* __restrict__ out) {
    int b = threadIdx.x;
    if (b >= BATCH) return;
    float P[KPT][3], Q[KPT][3];
    for (int k = 0; k < KPT; k++)
        for (int c = 0; c < 3; c++) {
            P[k][c] = g_Y[0][b][k][c];
            Q[k][c] = g_Y[1][b][k][c];
        }
    float c1[3] = {0, 0, 0}, c2[3] = {0, 0, 0};
    for (int k = 0; k < KPT; k++)
        for (int c = 0; c < 3; c++) { c1[c] += P[k][c]; c2[c] += Q[k][c]; }
    for (int c = 0; c < 3; c++) { c1[c] *= (1.0f / KPT); c2[c] *= (1.0f / KPT); }

    float Hm[3][3] = {{0,0,0},{0,0,0},{0,0,0}};
    for (int k = 0; k < KPT; k++)
        for (int i = 0; i < 3; i++)
            for (int j = 0; j < 3; j++)
                Hm[i][j] += (P[k][i] - c1[i]) * (Q[k][j] - c2[j]);

    float A[3][3];
    for (int i = 0; i < 3; i++)
        for (int j = 0; j < 3; j++) {
            float s = 0;
            for (int r = 0; r < 3; r++) s += Hm[r][i] * Hm[r][j];
            A[i][j] = s;
        }
    float V[3][3] = {{1,0,0},{0,1,0},{0,0,1}};
    for (int sweep = 0; sweep < 8; sweep++) {
        for (int pq = 0; pq < 3; pq++) {
            int p = (pq == 2) ? 1 : 0;
            int q = (pq == 0) ? 1 : 2;
            float apq = A[p][q];
            if (fabsf(apq) < 1e-35f) continue;
            float theta = (A[q][q] - A[p][p]) / (2.0f * apq);
            float tt = ((theta >= 0.f) ? 1.0f : -1.0f) / (fabsf(theta) + sqrtf(theta * theta + 1.0f));
            float cth = rsqrtf(tt * tt + 1.0f), sth = tt * cth;
            for (int i = 0; i < 3; i++) {
                float aip = A[i][p], aiq = A[i][q];
                A[i][p] = cth * aip - sth * aiq;
                A[i][q] = sth * aip + cth * aiq;
            }
            for (int i = 0; i < 3; i++) {
                float api = A[p][i], aqi = A[q][i];
                A[p][i] = cth * api - sth * aqi;
                A[q][i] = sth * api + cth * aqi;
            }
            for (int i = 0; i < 3; i++) {
                float vip = V[i][p], viq = V[i][q];
                V[i][p] = cth * vip - sth * viq;
                V[i][q] = sth * vip + cth * viq;
            }
        }
    }
    float w[3] = {A[0][0], A[1][1], A[2][2]};
    int idx[3] = {0, 1, 2};
    for (int i = 0; i < 2; i++)
        for (int j = i + 1; j < 3; j++)
            if (w[idx[j]] > w[idx[i]]) { int tmp = idx[i]; idx[i] = idx[j]; idx[j] = tmp; }
    float v0[3], v1[3], v2[3];
    for (int i = 0; i < 3; i++) {
        v0[i] = V[i][idx[0]]; v1[i] = V[i][idx[1]]; v2[i] = V[i][idx[2]];
    }
    float u0[3], u1[3], u2[3];
    for (int i = 0; i < 3; i++) {
        u0[i] = Hm[i][0] * v0[0] + Hm[i][1] * v0[1] + Hm[i][2] * v0[2];
        u1[i] = Hm[i][0] * v1[0] + Hm[i][1] * v1[1] + Hm[i][2] * v1[2];
    }
    float n0 = sqrtf(u0[0]*u0[0] + u0[1]*u0[1] + u0[2]*u0[2]);
    n0 = (n0 > 0.f) ? 1.0f / n0 : 0.0f;
    for (int i = 0; i < 3; i++) u0[i] *= n0;
    float d01 = u1[0]*u0[0] + u1[1]*u0[1] + u1[2]*u0[2];
    for (int i = 0; i < 3; i++) u1[i] -= d01 * u0[i];
    float n1 = sqrtf(u1[0]*u1[0] + u1[1]*u1[1] + u1[2]*u1[2]);
    n1 = (n1 > 0.f) ? 1.0f / n1 : 0.0f;
    for (int i = 0; i < 3; i++) u1[i] *= n1;
    u2[0] = u0[1]*u1[2] - u0[2]*u1[1];
    u2[1] = u0[2]*u1[0] - u0[0]*u1[2];
    u2[2] = u0[0]*u1[1] - u0[1]*u1[0];
    float cx = v1[1]*v2[2] - v1[2]*v2[1];
    float cy = v1[2]*v2[0] - v1[0]*v2[2];
    float cz = v1[0]*v2[1] - v1[1]*v2[0];
    float detV = v0[0]*cx + v0[1]*cy + v0[2]*cz;
    float s = (detV >= 0.f) ? 1.0f : -1.0f;

    float R[3][3];
    for (int i = 0; i < 3; i++)
        for (int j = 0; j < 3; j++)
            R[i][j] = u0[i]*v0[j] + u1[i]*v1[j] + s*u2[i]*v2[j];
    float tv[3];
    for (int j = 0; j < 3; j++)
        tv[j] = c2[j] - (c1[0]*R[0][j] + c1[1]*R[1][j] + c1[2]*R[2][j]);

    float* ob = out + b * 90;   // [3][K][3]
    for (int k = 0; k < KPT; k++)
        for (int c = 0; c < 3; c++) {
            ob[0 * 30 + k * 3 + c] = P[k][c];
            ob[1 * 30 + k * 3 + c] = Q[k][c];
        }
    for (int k = 0; k < KPT; k++)
        for (int j = 0; j < 3; j++) {
            float y = P[k][0]*R[0][j] + P[k][1]*R[1][j] + P[k][2]*R[2][j] + tv[j];
            ob[2 * 30 + k * 3 + j] = y;
        }
}

// ---------------- launch ----------------
extern "C" void kernel_launch(void* const* d_in, const int* in_sizes, int n_in,
                              void* d_out, int out_size) {
    const float* H1 = (const float*)d_in[0];
    const float* H2 = (const float*)d_in[1];
    const float* X1 = (const float*)d_in[2];
    const float* X2 = (const float*)d_in[3];
    const float* W1 = (const float*)d_in[4];
    const float* W2 = (const float*)d_in[5];
    float* out = (float*)d_out;

    // pass 1: column sums of H2 (128 MB)
    mean_kernel<<<dim3(MCH, BATCH), 256>>>(H2);
    // v1 = W1 @ mean(H2)
    v_kernel<<<dim3(KPT, BATCH), DIM>>>(W1, 0);
    // pass 2: side-0 scores over H1 + fused column sums of H1 (128 MB)
    score_kernel<<<dim3(NBLK, BATCH), 128>>>(H1, X1, 0);
    // v2 = W2 @ mean(H1)
    v_kernel<<<dim3(KPT, BATCH), DIM>>>(W2, 1);
    // pass 3: side-1 scores over H2 (128 MB)
    score_kernel<<<dim3(NBLK, BATCH), 128>>>(H2, X2, 1);
    combine_kernel<<<dim3(2, BATCH), 320>>>();
    kabsch_kernel<<<1, 32>>>(out);
}